// round 12
// baseline (speedup 1.0000x reference)
#include <cuda_runtime.h>
#include <math.h>

#define BATCH 16
#define DIM 48
#define HID 16
#define CH 8
#define IMH 256
#define IMW 256
#define HXW (IMH*IMW)
#define NPIX (BATCH*HXW)          // 1,048,576
#define PADW 264                  // padded plane row stride
#define PADH 258
#define PPLANE (PADH*PADW)
#define NTHREADS 256
#define PXT 4                     // pixels per thread in stage A

// scratch: LN'd x2 in zero-padded planes [ch][b][258][264]
// pixel (h,w) lives at padded (h+1, w+2); cols 0..1 and 258..263 stay zero,
// rows 0 and 257 stay zero => branchless 'SAME' padding.
__device__ __align__(16) float g_n[CH * BATCH * PPLANE];
// gate input x1 planar [ch][b][65536]
__device__ __align__(16) float g_x1[CH * BATCH * HXW];

typedef unsigned long long ull;

__device__ __forceinline__ ull bcast2(float a) {
    ull r; asm("mov.b64 %0, {%1, %1};" : "=l"(r) : "f"(a)); return r;
}
__device__ __forceinline__ void fma2(ull &d, ull a, ull b) {
    asm("fma.rn.f32x2 %0, %1, %2, %0;" : "+l"(d) : "l"(a), "l"(b));
}
__device__ __forceinline__ void unpack2(ull v, float &a, float &b) {
    asm("mov.b64 {%0, %1}, %2;" : "=f"(a), "=f"(b) : "l"(v));
}

__device__ __forceinline__ float gelu_exact(float v) {
    return 0.5f * v * (1.0f + erff(v * 0.70710678118654752f));
}

// ---------------- Kernel A: GEMM1 (packed f32x2, 4 px/thread) + gelu^2 + LN ----------------
__global__ __launch_bounds__(NTHREADS, 2)
void stage_a_kernel(const float* __restrict__ x,
                    const float* __restrict__ W1,
                    const float* __restrict__ b1,
                    const float* __restrict__ gamma,
                    const float* __restrict__ beta)
{
    __shared__ __align__(16) float sW1[DIM * HID];
    __shared__ __align__(16) float sb1[HID];
    __shared__ float sg[CH], sbt[CH];

    const int tid = threadIdx.x;
    for (int i = tid; i < DIM * HID; i += NTHREADS) sW1[i] = W1[i];
    if (tid < HID) sb1[tid] = b1[tid];
    if (tid < CH) { sg[tid] = gamma[tid]; sbt[tid] = beta[tid]; }
    __syncthreads();

    const int t  = blockIdx.x * NTHREADS + tid;
    const int p0 = t * PXT;                    // 4 consecutive pixels, same row
    const int b   = p0 >> 16;
    const int pos = p0 & (HXW - 1);
    const int h = pos >> 8;
    const int w = pos & 255;                   // multiple of 4

    ull acc[PXT][CH];
    {
        const ull* sb1p = (const ull*)sb1;
        #pragma unroll
        for (int i = 0; i < CH; i++) {
            const ull v = sb1p[i];
            #pragma unroll
            for (int px = 0; px < PXT; px++) acc[px][i] = v;
        }
    }

    #pragma unroll
    for (int dq = 0; dq < DIM / 4; dq++) {
        float4 xv[PXT];
        #pragma unroll
        for (int px = 0; px < PXT; px++)
            xv[px] = ((const float4*)(x + (size_t)(p0 + px) * DIM))[dq];

        #pragma unroll
        for (int j = 0; j < 4; j++) {
            // 4 x LDS.128 broadcast weight loads (8 packed pairs)
            ull wv[CH];
            {
                const ulonglong2* wr = (const ulonglong2*)&sW1[(dq * 4 + j) * HID];
                #pragma unroll
                for (int q = 0; q < 4; q++) {
                    const ulonglong2 wq = wr[q];
                    wv[2 * q] = wq.x; wv[2 * q + 1] = wq.y;
                }
            }
            #pragma unroll
            for (int px = 0; px < PXT; px++) {
                const float s = (j == 0) ? xv[px].x : (j == 1) ? xv[px].y
                              : (j == 2) ? xv[px].z : xv[px].w;
                const ull tb = bcast2(s);
                #pragma unroll
                for (int i = 0; i < CH; i++) fma2(acc[px][i], tb, wv[i]);
            }
        }
    }

    // epilogue per pixel
    float nv[PXT][CH], x1v[PXT][CH];

    #pragma unroll
    for (int px = 0; px < PXT; px++) {
        float af[HID];
        #pragma unroll
        for (int i = 0; i < CH; i++)
            unpack2(acc[px][i], af[2 * i], af[2 * i + 1]);

        #pragma unroll
        for (int hh = 0; hh < HID; hh++)
            af[hh] = gelu_exact(gelu_exact(af[hh]));

        float m = 0.0f;
        #pragma unroll
        for (int c = 0; c < CH; c++) m += af[CH + c];
        m *= (1.0f / CH);
        float var = 0.0f;
        #pragma unroll
        for (int c = 0; c < CH; c++) { float d = af[CH + c] - m; var += d * d; }
        var *= (1.0f / CH);
        const float inv = rsqrtf(var + 1e-5f);

        #pragma unroll
        for (int c = 0; c < CH; c++) {
            nv[px][c]  = (af[CH + c] - m) * inv * sg[c] + sbt[c];
            x1v[px][c] = af[c];
        }
    }

    // stores: g_n at padded col w+2 (8B aligned) as two float2 per channel;
    //         g_x1 at p0 (16B aligned) as one float4 per channel
    const int padidx = b * PPLANE + (h + 1) * PADW + (w + 2);
    #pragma unroll
    for (int c = 0; c < CH; c++) {
        float* npt = &g_n[(size_t)c * (BATCH * PPLANE) + padidx];
        *(float2*)npt       = make_float2(nv[0][c], nv[1][c]);
        *(float2*)(npt + 2) = make_float2(nv[2][c], nv[3][c]);
    }
    #pragma unroll
    for (int c = 0; c < CH; c++) {
        float4 xo = {x1v[0][c], x1v[1][c], x1v[2][c], x1v[3][c]};
        *(float4*)&g_x1[(size_t)c * NPIX + p0] = xo;
    }
}

// ---------------- Kernel B: conv + gate + GEMM2, 4 px/thread, vector loads ----------------
__global__ __launch_bounds__(NTHREADS, 2)
void stage_b_kernel(const float* __restrict__ dww,
                    const float* __restrict__ dwb,
                    const float* __restrict__ pww,
                    const float* __restrict__ pwb,
                    const float* __restrict__ W2,
                    const float* __restrict__ b2,
                    float* __restrict__ out)
{
    __shared__ float sW2[CH * DIM];
    __shared__ float sb2[DIM];
    __shared__ float sdw[CH * 9], sdwb[CH];
    __shared__ float spw[CH * CH], spwb[CH];

    const int tid = threadIdx.x;
    for (int i = tid; i < CH * DIM; i += NTHREADS) sW2[i] = W2[i];
    if (tid < DIM) sb2[tid] = b2[tid];
    if (tid < CH) { sdwb[tid] = dwb[tid]; spwb[tid] = pwb[tid]; }
    for (int i = tid; i < CH * 9;  i += NTHREADS) sdw[i] = dww[i];
    for (int i = tid; i < CH * CH; i += NTHREADS) spw[i] = pww[i];
    __syncthreads();

    const int t  = blockIdx.x * NTHREADS + tid;
    const int p0 = t * 4;                       // 4 consecutive pixels, same row
    const int b   = p0 >> 16;
    const int pos = p0 & (HXW - 1);
    const int h  = pos >> 8;
    const int w0 = pos & 255;                   // multiple of 4

    const int rb = b * PPLANE + h * PADW + w0;

    float sp[CH][4];     // depthwise results
    float nc[CH][4];     // center values (for pointwise)

    #pragma unroll
    for (int c = 0; c < CH; c++) {
        const float* __restrict__ np = &g_n[(size_t)c * (BATCH * PPLANE) + rb];

        const float4 r0a = *(const float4*)np;
        const float4 r0b = *(const float4*)(np + 4);
        const float4 r1a = *(const float4*)(np + PADW);
        const float4 r1b = *(const float4*)(np + PADW + 4);
        const float4 r2a = *(const float4*)(np + 2 * PADW);
        const float4 r2b = *(const float4*)(np + 2 * PADW + 4);

        const float v0[8] = {r0a.x, r0a.y, r0a.z, r0a.w, r0b.x, r0b.y, r0b.z, r0b.w};
        const float v1[8] = {r1a.x, r1a.y, r1a.z, r1a.w, r1b.x, r1b.y, r1b.z, r1b.w};
        const float v2[8] = {r2a.x, r2a.y, r2a.z, r2a.w, r2b.x, r2b.y, r2b.z, r2b.w};

        const float* kw = &sdw[c * 9];
        #pragma unroll
        for (int i = 0; i < 4; i++) {
            float s = sdwb[c];
            s += v0[i + 1] * kw[0]; s += v0[i + 2] * kw[1]; s += v0[i + 3] * kw[2];
            s += v1[i + 1] * kw[3]; s += v1[i + 2] * kw[4]; s += v1[i + 3] * kw[5];
            s += v2[i + 1] * kw[6]; s += v2[i + 2] * kw[7]; s += v2[i + 3] * kw[8];
            sp[c][i] = s;
            nc[c][i] = v1[i + 2];
        }
    }

    float g[CH][4];
    #pragma unroll
    for (int c = 0; c < CH; c++) {
        float ch0 = spwb[c], ch1 = spwb[c], ch2 = spwb[c], ch3 = spwb[c];
        #pragma unroll
        for (int ci = 0; ci < CH; ci++) {
            const float wv = spw[c * CH + ci];
            ch0 += wv * nc[ci][0];
            ch1 += wv * nc[ci][1];
            ch2 += wv * nc[ci][2];
            ch3 += wv * nc[ci][3];
        }
        const float4 x1v = *(const float4*)&g_x1[(size_t)c * NPIX + p0];
        g[c][0] = x1v.x * sp[c][0] * ch0;
        g[c][1] = x1v.y * sp[c][1] * ch1;
        g[c][2] = x1v.z * sp[c][2] * ch2;
        g[c][3] = x1v.w * sp[c][3] * ch3;
    }

    float* __restrict__ outb = out + (size_t)b * (DIM * HXW) + pos;

    #pragma unroll
    for (int dc = 0; dc < DIM / 4; dc++) {
        float o[4][4];
        #pragma unroll
        for (int j = 0; j < 4; j++) {
            const float bv = sb2[dc * 4 + j];
            o[j][0] = bv; o[j][1] = bv; o[j][2] = bv; o[j][3] = bv;
        }
        #pragma unroll
        for (int c = 0; c < CH; c++) {
            #pragma unroll
            for (int j = 0; j < 4; j++) {
                const float wv = sW2[c * DIM + dc * 4 + j];
                o[j][0] += g[c][0] * wv;
                o[j][1] += g[c][1] * wv;
                o[j][2] += g[c][2] * wv;
                o[j][3] += g[c][3] * wv;
            }
        }
        #pragma unroll
        for (int j = 0; j < 4; j++) {
            float4 ov = {o[j][0], o[j][1], o[j][2], o[j][3]};
            *(float4*)(outb + (size_t)(dc * 4 + j) * HXW) = ov;
        }
    }
}

extern "C" void kernel_launch(void* const* d_in, const int* in_sizes, int n_in,
                              void* d_out, int out_size)
{
    const float* x     = (const float*)d_in[0];
    const float* W1    = (const float*)d_in[1];
    const float* b1    = (const float*)d_in[2];
    const float* gamma = (const float*)d_in[3];
    const float* beta  = (const float*)d_in[4];
    const float* dww   = (const float*)d_in[5];
    const float* dwb   = (const float*)d_in[6];
    const float* pww   = (const float*)d_in[7];
    const float* pwb   = (const float*)d_in[8];
    const float* W2    = (const float*)d_in[9];
    const float* b2    = (const float*)d_in[10];
    float* out = (float*)d_out;

    stage_a_kernel<<<NPIX / PXT / NTHREADS, NTHREADS>>>(x, W1, b1, gamma, beta);
    stage_b_kernel<<<NPIX / 4 / NTHREADS, NTHREADS>>>(dww, dwb, pww, pwb, W2, b2, out);
}